// round 1
// baseline (speedup 1.0000x reference)
#include <cuda_runtime.h>
#include <stdint.h>

// MLPTexture3D: fused instant-NGP hashgrid encode (L=16, T=2^19) + MLP(32-32-32-9) + sigmoid.
// One thread per point. Grid table (64MB) stays L2-resident; texc/out use streaming hints.

constexpr int NLVL = 16;
constexpr uint32_t TBL = 1u << 19;
constexpr uint32_t TBLMASK = TBL - 1u;

__global__ void __launch_bounds__(256)
fused_ngp_mlp(const float* __restrict__ texc,
              const float* __restrict__ grid,
              const float* __restrict__ W0,
              const float* __restrict__ W1,
              const float* __restrict__ W2,
              const float* __restrict__ AABB,
              const float* __restrict__ minmax,
              float* __restrict__ out,
              int N)
{
    __shared__ __align__(16) float sW0[1024];
    __shared__ __align__(16) float sW1[1024];
    __shared__ __align__(16) float sW2[288];
    __shared__ float sA[6];
    __shared__ float sLo[9];
    __shared__ float sDf[9];

    const int tid = threadIdx.x;
    for (int i = tid; i < 1024; i += 256) { sW0[i] = W0[i]; sW1[i] = W1[i]; }
    if (tid < 288) sW2[tid] = W2[tid];
    if (tid < 6)  sA[tid] = AABB[tid];
    if (tid < 9)  { float lo = minmax[tid]; sLo[tid] = lo; sDf[tid] = minmax[9 + tid] - lo; }
    __syncthreads();

    const int n = blockIdx.x * 256 + tid;
    if (n >= N) return;

    float ux, uy, uz;
    {
        const float tx = __ldcs(texc + 3 * n + 0);
        const float ty = __ldcs(texc + 3 * n + 1);
        const float tz = __ldcs(texc + 3 * n + 2);
        ux = __saturatef((tx - sA[0]) / (sA[3] - sA[0]));
        uy = __saturatef((ty - sA[1]) / (sA[4] - sA[1]));
        uz = __saturatef((tz - sA[2]) / (sA[5] - sA[2]));
    }

    float feats[32];

#pragma unroll
    for (int l = 0; l < NLVL; ++l) {
        const float scale = 16.0f * exp2f((float)l * (8.0f / 15.0f)) - 1.0f;
        const float posx = ux * scale + 0.5f;
        const float posy = uy * scale + 0.5f;
        const float posz = uz * scale + 0.5f;
        const float flx = floorf(posx), fly = floorf(posy), flz = floorf(posz);
        const float rx = posx - flx, ry = posy - fly, rz = posz - flz;
        const uint32_t ix = (uint32_t)flx, iy = (uint32_t)fly, iz = (uint32_t)flz;

        uint32_t idx[8];
        if (l < 5) {
            // dense levels: res = {16,24,34,49,71}, res^3 <= T
            const uint32_t R = (l == 0) ? 16u : (l == 1) ? 24u : (l == 2) ? 34u
                              : (l == 3) ? 49u : 71u;
            const uint32_t rm = R - 1u;
            const uint32_t x0 = min(ix, rm),            x1 = min(ix + 1u, rm);
            const uint32_t y0 = min(iy, rm) * R,        y1 = min(iy + 1u, rm) * R;
            const uint32_t z0 = min(iz, rm) * (R * R),  z1 = min(iz + 1u, rm) * (R * R);
            idx[0] = x0 + y0 + z0; idx[1] = x1 + y0 + z0;
            idx[2] = x0 + y1 + z0; idx[3] = x1 + y1 + z0;
            idx[4] = x0 + y0 + z1; idx[5] = x1 + y0 + z1;
            idx[6] = x0 + y1 + z1; idx[7] = x1 + y1 + z1;
        } else {
            const uint32_t hx0 = ix, hx1 = ix + 1u;
            const uint32_t hy0 = iy * 2654435761u, hy1 = hy0 + 2654435761u;
            const uint32_t hz0 = iz * 805459861u,  hz1 = hz0 + 805459861u;
            idx[0] = (hx0 ^ hy0 ^ hz0) & TBLMASK;
            idx[1] = (hx1 ^ hy0 ^ hz0) & TBLMASK;
            idx[2] = (hx0 ^ hy1 ^ hz0) & TBLMASK;
            idx[3] = (hx1 ^ hy1 ^ hz0) & TBLMASK;
            idx[4] = (hx0 ^ hy0 ^ hz1) & TBLMASK;
            idx[5] = (hx1 ^ hy0 ^ hz1) & TBLMASK;
            idx[6] = (hx0 ^ hy1 ^ hz1) & TBLMASK;
            idx[7] = (hx1 ^ hy1 ^ hz1) & TBLMASK;
        }

        const float2* __restrict__ gl =
            reinterpret_cast<const float2*>(grid) + (size_t)l * TBL;
        float2 g[8];
#pragma unroll
        for (int c = 0; c < 8; ++c) g[c] = __ldg(gl + idx[c]);

        const float wx0 = 1.0f - rx, wy0 = 1.0f - ry, wz0 = 1.0f - rz;
        const float w00 = wx0 * wy0, w10 = rx * wy0, w01 = wx0 * ry, w11 = rx * ry;
        const float a0 = w00 * wz0, a1 = w10 * wz0, a2 = w01 * wz0, a3 = w11 * wz0;
        const float b0 = w00 * rz,  b1 = w10 * rz,  b2 = w01 * rz,  b3 = w11 * rz;

        float f0 = a0 * g[0].x;     float f1 = a0 * g[0].y;
        f0 = fmaf(a1, g[1].x, f0);  f1 = fmaf(a1, g[1].y, f1);
        f0 = fmaf(a2, g[2].x, f0);  f1 = fmaf(a2, g[2].y, f1);
        f0 = fmaf(a3, g[3].x, f0);  f1 = fmaf(a3, g[3].y, f1);
        f0 = fmaf(b0, g[4].x, f0);  f1 = fmaf(b0, g[4].y, f1);
        f0 = fmaf(b1, g[5].x, f0);  f1 = fmaf(b1, g[5].y, f1);
        f0 = fmaf(b2, g[6].x, f0);  f1 = fmaf(b2, g[6].y, f1);
        f0 = fmaf(b3, g[7].x, f0);  f1 = fmaf(b3, g[7].y, f1);

        feats[2 * l]     = f0;
        feats[2 * l + 1] = f1;
    }

    // ---- MLP layer 0: h = relu(feats @ W0^T) ----
    float h[32];
#pragma unroll
    for (int j = 0; j < 32; ++j) {
        const float4* wr = reinterpret_cast<const float4*>(sW0 + j * 32);
        float s0 = 0.0f, s1 = 0.0f;
#pragma unroll
        for (int i = 0; i < 8; ++i) {
            const float4 w4 = wr[i];
            s0 = fmaf(feats[4 * i + 0], w4.x, s0);
            s1 = fmaf(feats[4 * i + 1], w4.y, s1);
            s0 = fmaf(feats[4 * i + 2], w4.z, s0);
            s1 = fmaf(feats[4 * i + 3], w4.w, s1);
        }
        h[j] = fmaxf(s0 + s1, 0.0f);
    }

    // ---- MLP layer 1: h2 = relu(h @ W1^T) ----
    float h2[32];
#pragma unroll
    for (int j = 0; j < 32; ++j) {
        const float4* wr = reinterpret_cast<const float4*>(sW1 + j * 32);
        float s0 = 0.0f, s1 = 0.0f;
#pragma unroll
        for (int i = 0; i < 8; ++i) {
            const float4 w4 = wr[i];
            s0 = fmaf(h[4 * i + 0], w4.x, s0);
            s1 = fmaf(h[4 * i + 1], w4.y, s1);
            s0 = fmaf(h[4 * i + 2], w4.z, s0);
            s1 = fmaf(h[4 * i + 3], w4.w, s1);
        }
        h2[j] = fmaxf(s0 + s1, 0.0f);
    }

    // ---- MLP layer 2 + sigmoid + min/max scale ----
#pragma unroll
    for (int k = 0; k < 9; ++k) {
        const float4* wr = reinterpret_cast<const float4*>(sW2 + k * 32);
        float s0 = 0.0f, s1 = 0.0f;
#pragma unroll
        for (int i = 0; i < 8; ++i) {
            const float4 w4 = wr[i];
            s0 = fmaf(h2[4 * i + 0], w4.x, s0);
            s1 = fmaf(h2[4 * i + 1], w4.y, s1);
            s0 = fmaf(h2[4 * i + 2], w4.z, s0);
            s1 = fmaf(h2[4 * i + 3], w4.w, s1);
        }
        const float o = s0 + s1;
        const float sig = 1.0f / (1.0f + __expf(-o));
        __stcs(out + (size_t)n * 9 + k, fmaf(sig, sDf[k], sLo[k]));
    }
}

extern "C" void kernel_launch(void* const* d_in, const int* in_sizes, int n_in,
                              void* d_out, int out_size) {
    const float* texc   = (const float*)d_in[0];
    const float* grid   = (const float*)d_in[1];
    const float* W0     = (const float*)d_in[2];
    const float* W1     = (const float*)d_in[3];
    const float* W2     = (const float*)d_in[4];
    const float* AABB   = (const float*)d_in[5];
    const float* minmax = (const float*)d_in[6];
    float* out = (float*)d_out;

    const int N = in_sizes[0] / 3;
    const int blocks = (N + 255) / 256;
    fused_ngp_mlp<<<blocks, 256>>>(texc, grid, W0, W1, W2, AABB, minmax, out, N);
}

// round 2
// speedup vs baseline: 1.0807x; 1.0807x over previous
#include <cuda_runtime.h>
#include <stdint.h>

// MLPTexture3D: fused instant-NGP hashgrid encode (L=16, T=2^19) + MLP(32-32-32-9) + sigmoid.
// R2: x-corner pair gathers via aligned float4 loads (-25% L1tex wavefronts).

constexpr int NLVL = 16;
constexpr uint32_t TBL = 1u << 19;
constexpr uint32_t TBLMASK = TBL - 1u;

__global__ void __launch_bounds__(256)
fused_ngp_mlp(const float* __restrict__ texc,
              const float* __restrict__ grid,
              const float* __restrict__ W0,
              const float* __restrict__ W1,
              const float* __restrict__ W2,
              const float* __restrict__ AABB,
              const float* __restrict__ minmax,
              float* __restrict__ out,
              int N)
{
    __shared__ __align__(16) float sW0[1024];
    __shared__ __align__(16) float sW1[1024];
    __shared__ __align__(16) float sW2[288];
    __shared__ float sA[6];
    __shared__ float sLo[9];
    __shared__ float sDf[9];

    const int tid = threadIdx.x;
    for (int i = tid; i < 1024; i += 256) { sW0[i] = W0[i]; sW1[i] = W1[i]; }
    if (tid < 288) sW2[tid] = W2[tid];
    if (tid < 6)  sA[tid] = AABB[tid];
    if (tid < 9)  { float lo = minmax[tid]; sLo[tid] = lo; sDf[tid] = minmax[9 + tid] - lo; }
    __syncthreads();

    const int n = blockIdx.x * 256 + tid;
    if (n >= N) return;

    float ux, uy, uz;
    {
        const float tx = __ldcs(texc + 3 * n + 0);
        const float ty = __ldcs(texc + 3 * n + 1);
        const float tz = __ldcs(texc + 3 * n + 2);
        ux = __saturatef((tx - sA[0]) / (sA[3] - sA[0]));
        uy = __saturatef((ty - sA[1]) / (sA[4] - sA[1]));
        uz = __saturatef((tz - sA[2]) / (sA[5] - sA[2]));
    }

    float feats[32];

#pragma unroll
    for (int l = 0; l < NLVL; ++l) {
        const float scale = 16.0f * exp2f((float)l * (8.0f / 15.0f)) - 1.0f;
        const float posx = ux * scale + 0.5f;
        const float posy = uy * scale + 0.5f;
        const float posz = uz * scale + 0.5f;
        const float flx = floorf(posx), fly = floorf(posy), flz = floorf(posz);
        const float rx = posx - flx, ry = posy - fly, rz = posz - flz;
        const uint32_t ix = (uint32_t)flx, iy = (uint32_t)fly, iz = (uint32_t)flz;

        // idx0[c] = x0-corner index for (y,z)-combo c; idx1[c] = x1-corner.
        uint32_t i0[4], i1[4];
        if (l < 5) {
            const uint32_t R = (l == 0) ? 16u : (l == 1) ? 24u : (l == 2) ? 34u
                              : (l == 3) ? 49u : 71u;
            const uint32_t rm = R - 1u;
            const uint32_t x0 = min(ix, rm),            x1 = min(ix + 1u, rm);
            const uint32_t y0 = min(iy, rm) * R,        y1 = min(iy + 1u, rm) * R;
            const uint32_t z0 = min(iz, rm) * (R * R),  z1 = min(iz + 1u, rm) * (R * R);
            i0[0] = x0 + y0 + z0;  i1[0] = x1 + y0 + z0;
            i0[1] = x0 + y1 + z0;  i1[1] = x1 + y1 + z0;
            i0[2] = x0 + y0 + z1;  i1[2] = x1 + y0 + z1;
            i0[3] = x0 + y1 + z1;  i1[3] = x1 + y1 + z1;
        } else {
            const uint32_t hx0 = ix, hx1 = ix + 1u;
            const uint32_t hy0 = iy * 2654435761u, hy1 = hy0 + 2654435761u;
            const uint32_t hz0 = iz * 805459861u,  hz1 = hz0 + 805459861u;
            const uint32_t b00 = hy0 ^ hz0, b10 = hy1 ^ hz0;
            const uint32_t b01 = hy0 ^ hz1, b11 = hy1 ^ hz1;
            i0[0] = (hx0 ^ b00) & TBLMASK;  i1[0] = (hx1 ^ b00) & TBLMASK;
            i0[1] = (hx0 ^ b10) & TBLMASK;  i1[1] = (hx1 ^ b10) & TBLMASK;
            i0[2] = (hx0 ^ b01) & TBLMASK;  i1[2] = (hx1 ^ b01) & TBLMASK;
            i0[3] = (hx0 ^ b11) & TBLMASK;  i1[3] = (hx1 ^ b11) & TBLMASK;
        }

        const float2* __restrict__ gl =
            reinterpret_cast<const float2*>(grid) + (size_t)l * TBL;
        const float4* __restrict__ gl4 = reinterpret_cast<const float4*>(gl);

        // Gather 4 x-pairs. One aligned float4 always; predicated float2 when
        // the x1 corner lands in a different 16B slot.
        float2 c0[4], c1[4];
#pragma unroll
        for (int c = 0; c < 4; ++c) {
            const uint32_t s0 = i0[c] >> 1;
            const float4 q = __ldg(gl4 + s0);
            c0[c] = (i0[c] & 1u) ? make_float2(q.z, q.w) : make_float2(q.x, q.y);
            if ((i1[c] >> 1) == s0) {
                c1[c] = (i1[c] & 1u) ? make_float2(q.z, q.w) : make_float2(q.x, q.y);
            } else {
                c1[c] = __ldg(gl + i1[c]);
            }
        }

        const float wx0 = 1.0f - rx, wy0 = 1.0f - ry, wz0 = 1.0f - rz;
        // pair c weights: (y,z) combos in order (y0,z0),(y1,z0),(y0,z1),(y1,z1)
        const float pw[4] = { wy0 * wz0, ry * wz0, wy0 * rz, ry * rz };

        float f0 = 0.0f, f1 = 0.0f;
#pragma unroll
        for (int c = 0; c < 4; ++c) {
            const float w0c = pw[c] * wx0;
            const float w1c = pw[c] * rx;
            f0 = fmaf(w0c, c0[c].x, f0);  f1 = fmaf(w0c, c0[c].y, f1);
            f0 = fmaf(w1c, c1[c].x, f0);  f1 = fmaf(w1c, c1[c].y, f1);
        }

        feats[2 * l]     = f0;
        feats[2 * l + 1] = f1;
    }

    // ---- MLP layer 0: h = relu(feats @ W0^T) ----
    float h[32];
#pragma unroll
    for (int j = 0; j < 32; ++j) {
        const float4* wr = reinterpret_cast<const float4*>(sW0 + j * 32);
        float s0 = 0.0f, s1 = 0.0f;
#pragma unroll
        for (int i = 0; i < 8; ++i) {
            const float4 w4 = wr[i];
            s0 = fmaf(feats[4 * i + 0], w4.x, s0);
            s1 = fmaf(feats[4 * i + 1], w4.y, s1);
            s0 = fmaf(feats[4 * i + 2], w4.z, s0);
            s1 = fmaf(feats[4 * i + 3], w4.w, s1);
        }
        h[j] = fmaxf(s0 + s1, 0.0f);
    }

    // ---- MLP layer 1: h2 = relu(h @ W1^T) ----
    float h2[32];
#pragma unroll
    for (int j = 0; j < 32; ++j) {
        const float4* wr = reinterpret_cast<const float4*>(sW1 + j * 32);
        float s0 = 0.0f, s1 = 0.0f;
#pragma unroll
        for (int i = 0; i < 8; ++i) {
            const float4 w4 = wr[i];
            s0 = fmaf(h[4 * i + 0], w4.x, s0);
            s1 = fmaf(h[4 * i + 1], w4.y, s1);
            s0 = fmaf(h[4 * i + 2], w4.z, s0);
            s1 = fmaf(h[4 * i + 3], w4.w, s1);
        }
        h2[j] = fmaxf(s0 + s1, 0.0f);
    }

    // ---- MLP layer 2 + sigmoid + min/max scale ----
#pragma unroll
    for (int k = 0; k < 9; ++k) {
        const float4* wr = reinterpret_cast<const float4*>(sW2 + k * 32);
        float s0 = 0.0f, s1 = 0.0f;
#pragma unroll
        for (int i = 0; i < 8; ++i) {
            const float4 w4 = wr[i];
            s0 = fmaf(h2[4 * i + 0], w4.x, s0);
            s1 = fmaf(h2[4 * i + 1], w4.y, s1);
            s0 = fmaf(h2[4 * i + 2], w4.z, s0);
            s1 = fmaf(h2[4 * i + 3], w4.w, s1);
        }
        const float o = s0 + s1;
        const float sig = 1.0f / (1.0f + __expf(-o));
        __stcs(out + (size_t)n * 9 + k, fmaf(sig, sDf[k], sLo[k]));
    }
}

extern "C" void kernel_launch(void* const* d_in, const int* in_sizes, int n_in,
                              void* d_out, int out_size) {
    const float* texc   = (const float*)d_in[0];
    const float* grid   = (const float*)d_in[1];
    const float* W0     = (const float*)d_in[2];
    const float* W1     = (const float*)d_in[3];
    const float* W2     = (const float*)d_in[4];
    const float* AABB   = (const float*)d_in[5];
    const float* minmax = (const float*)d_in[6];
    float* out = (float*)d_out;

    const int N = in_sizes[0] / 3;
    const int blocks = (N + 255) / 256;
    fused_ngp_mlp<<<blocks, 256>>>(texc, grid, W0, W1, W2, AABB, minmax, out, N);
}

// round 3
// speedup vs baseline: 1.0979x; 1.0159x over previous
#include <cuda_runtime.h>
#include <cuda_bf16.h>
#include <stdint.h>

// MLPTexture3D fused instant-NGP hashgrid (L=16, T=2^19) + MLP(32-32-32-9) + sigmoid.
// R3: grid repacked into bf16 overlapping-pair table: slot k = (e[k], e[k+1]) in 8B.
// Every trilinear x-pair (dense i0/i0+1, hashed i0/i0^1) = ONE 8B gather.

constexpr int NLVL = 16;
constexpr uint32_t TBL = 1u << 19;
constexpr uint32_t TBLMASK = TBL - 1u;
constexpr uint32_t NSLOT = (uint32_t)NLVL * TBL;

__device__ __align__(16) uint2 gPair[NSLOT];   // 64 MB scratch table

__global__ void __launch_bounds__(256)
repack_grid(const float2* __restrict__ grid)
{
    const uint32_t k = blockIdx.x * 256u + threadIdx.x;
    if (k >= NSLOT) return;
    const uint32_t lk = k & TBLMASK;
    const float2 e0 = __ldcs(grid + k);
    const float2 e1 = (lk + 1u < TBL) ? __ldcs(grid + k + 1u) : e0;
    const __nv_bfloat162 b0 = __float22bfloat162_rn(e0);
    const __nv_bfloat162 b1 = __float22bfloat162_rn(e1);
    uint2 o;
    o.x = *reinterpret_cast<const uint32_t*>(&b0);
    o.y = *reinterpret_cast<const uint32_t*>(&b1);
    gPair[k] = o;
}

__global__ void __launch_bounds__(256)
fused_ngp_mlp(const float* __restrict__ texc,
              const float* __restrict__ W0,
              const float* __restrict__ W1,
              const float* __restrict__ W2,
              const float* __restrict__ AABB,
              const float* __restrict__ minmax,
              float* __restrict__ out,
              int N)
{
    __shared__ __align__(16) float sW0[1024];
    __shared__ __align__(16) float sW1[1024];
    __shared__ __align__(16) float sW2[288];
    __shared__ float sA[6];
    __shared__ float sLo[9];
    __shared__ float sDf[9];

    const int tid = threadIdx.x;
    for (int i = tid; i < 1024; i += 256) { sW0[i] = W0[i]; sW1[i] = W1[i]; }
    if (tid < 288) sW2[tid] = W2[tid];
    if (tid < 6)  sA[tid] = AABB[tid];
    if (tid < 9)  { float lo = minmax[tid]; sLo[tid] = lo; sDf[tid] = minmax[9 + tid] - lo; }
    __syncthreads();

    const int n = blockIdx.x * 256 + tid;
    if (n >= N) return;

    float ux, uy, uz;
    {
        const float tx = __ldcs(texc + 3 * n + 0);
        const float ty = __ldcs(texc + 3 * n + 1);
        const float tz = __ldcs(texc + 3 * n + 2);
        ux = __saturatef((tx - sA[0]) / (sA[3] - sA[0]));
        uy = __saturatef((ty - sA[1]) / (sA[4] - sA[1]));
        uz = __saturatef((tz - sA[2]) / (sA[5] - sA[2]));
    }

    float feats[32];

#pragma unroll
    for (int l = 0; l < NLVL; ++l) {
        const float scale = 16.0f * exp2f((float)l * (8.0f / 15.0f)) - 1.0f;
        const float posx = ux * scale + 0.5f;
        const float posy = uy * scale + 0.5f;
        const float posz = uz * scale + 0.5f;
        const float flx = floorf(posx), fly = floorf(posy), flz = floorf(posz);
        const float rx = posx - flx, ry = posy - fly, rz = posz - flz;
        const uint32_t ix = (uint32_t)flx, iy = (uint32_t)fly, iz = (uint32_t)flz;

        // slot[c]: pair-table slot; hiA/hiB[c]: does corner x0/x1 take the hi entry?
        uint32_t slot[4];
        bool hiA[4], hiB[4];
        if (l < 5) {
            const uint32_t R = (l == 0) ? 16u : (l == 1) ? 24u : (l == 2) ? 34u
                              : (l == 3) ? 49u : 71u;
            const uint32_t rm = R - 1u;
            const uint32_t x0 = min(ix, rm),            x1 = min(ix + 1u, rm);
            const uint32_t y0 = min(iy, rm) * R,        y1 = min(iy + 1u, rm) * R;
            const uint32_t z0 = min(iz, rm) * (R * R),  z1 = min(iz + 1u, rm) * (R * R);
            const bool adv = (x1 > x0);   // x1 corner = slot's hi entry iff not clamped
            slot[0] = x0 + y0 + z0;  slot[1] = x0 + y1 + z0;
            slot[2] = x0 + y0 + z1;  slot[3] = x0 + y1 + z1;
#pragma unroll
            for (int c = 0; c < 4; ++c) { hiA[c] = false; hiB[c] = adv; }
        } else {
            const uint32_t hy0 = iy * 2654435761u, hy1 = hy0 + 2654435761u;
            const uint32_t hz0 = iz * 805459861u,  hz1 = hz0 + 805459861u;
            const uint32_t b00 = hy0 ^ hz0, b10 = hy1 ^ hz0;
            const uint32_t b01 = hy0 ^ hz1, b11 = hy1 ^ hz1;
            const uint32_t a0 = (ix ^ b00) & TBLMASK;
            const uint32_t a1 = (ix ^ b10) & TBLMASK;
            const uint32_t a2 = (ix ^ b01) & TBLMASK;
            const uint32_t a3 = (ix ^ b11) & TBLMASK;
            slot[0] = a0 & ~1u; slot[1] = a1 & ~1u;
            slot[2] = a2 & ~1u; slot[3] = a3 & ~1u;
            // x1 index = a^1; x0 takes hi when a odd, x1 takes the other half.
            hiA[0] = a0 & 1u; hiA[1] = a1 & 1u; hiA[2] = a2 & 1u; hiA[3] = a3 & 1u;
#pragma unroll
            for (int c = 0; c < 4; ++c) hiB[c] = !hiA[c];
        }

        const uint2* __restrict__ gl = gPair + (size_t)l * TBL;
        uint2 q[4];
#pragma unroll
        for (int c = 0; c < 4; ++c) q[c] = __ldg(gl + slot[c]);

        const float wx0 = 1.0f - rx, wy0 = 1.0f - ry, wz0 = 1.0f - rz;
        const float pw[4] = { wy0 * wz0, ry * wz0, wy0 * rz, ry * rz };

        float f0 = 0.0f, f1 = 0.0f;
#pragma unroll
        for (int c = 0; c < 4; ++c) {
            const uint32_t pa = hiA[c] ? q[c].y : q[c].x;
            const uint32_t pb = hiB[c] ? q[c].y : q[c].x;
            const float2 va = __bfloat1622float2(
                *reinterpret_cast<const __nv_bfloat162*>(&pa));
            const float2 vb = __bfloat1622float2(
                *reinterpret_cast<const __nv_bfloat162*>(&pb));
            const float w0c = pw[c] * wx0;
            const float w1c = pw[c] * rx;
            f0 = fmaf(w0c, va.x, f0);  f1 = fmaf(w0c, va.y, f1);
            f0 = fmaf(w1c, vb.x, f0);  f1 = fmaf(w1c, vb.y, f1);
        }

        feats[2 * l]     = f0;
        feats[2 * l + 1] = f1;
    }

    // ---- MLP layer 0 ----
    float h[32];
#pragma unroll
    for (int j = 0; j < 32; ++j) {
        const float4* wr = reinterpret_cast<const float4*>(sW0 + j * 32);
        float s0 = 0.0f, s1 = 0.0f;
#pragma unroll
        for (int i = 0; i < 8; ++i) {
            const float4 w4 = wr[i];
            s0 = fmaf(feats[4 * i + 0], w4.x, s0);
            s1 = fmaf(feats[4 * i + 1], w4.y, s1);
            s0 = fmaf(feats[4 * i + 2], w4.z, s0);
            s1 = fmaf(feats[4 * i + 3], w4.w, s1);
        }
        h[j] = fmaxf(s0 + s1, 0.0f);
    }

    // ---- MLP layer 1 ----
    float h2[32];
#pragma unroll
    for (int j = 0; j < 32; ++j) {
        const float4* wr = reinterpret_cast<const float4*>(sW1 + j * 32);
        float s0 = 0.0f, s1 = 0.0f;
#pragma unroll
        for (int i = 0; i < 8; ++i) {
            const float4 w4 = wr[i];
            s0 = fmaf(h[4 * i + 0], w4.x, s0);
            s1 = fmaf(h[4 * i + 1], w4.y, s1);
            s0 = fmaf(h[4 * i + 2], w4.z, s0);
            s1 = fmaf(h[4 * i + 3], w4.w, s1);
        }
        h2[j] = fmaxf(s0 + s1, 0.0f);
    }

    // ---- MLP layer 2 + sigmoid + min/max scale ----
#pragma unroll
    for (int k = 0; k < 9; ++k) {
        const float4* wr = reinterpret_cast<const float4*>(sW2 + k * 32);
        float s0 = 0.0f, s1 = 0.0f;
#pragma unroll
        for (int i = 0; i < 8; ++i) {
            const float4 w4 = wr[i];
            s0 = fmaf(h2[4 * i + 0], w4.x, s0);
            s1 = fmaf(h2[4 * i + 1], w4.y, s1);
            s0 = fmaf(h2[4 * i + 2], w4.z, s0);
            s1 = fmaf(h2[4 * i + 3], w4.w, s1);
        }
        const float o = s0 + s1;
        const float sig = 1.0f / (1.0f + __expf(-o));
        __stcs(out + (size_t)n * 9 + k, fmaf(sig, sDf[k], sLo[k]));
    }
}

extern "C" void kernel_launch(void* const* d_in, const int* in_sizes, int n_in,
                              void* d_out, int out_size) {
    const float* texc   = (const float*)d_in[0];
    const float* grid   = (const float*)d_in[1];
    const float* W0     = (const float*)d_in[2];
    const float* W1     = (const float*)d_in[3];
    const float* W2     = (const float*)d_in[4];
    const float* AABB   = (const float*)d_in[5];
    const float* minmax = (const float*)d_in[6];
    float* out = (float*)d_out;

    const int N = in_sizes[0] / 3;

    repack_grid<<<(NSLOT + 255u) / 256u, 256>>>(
        reinterpret_cast<const float2*>(grid));

    const int blocks = (N + 255) / 256;
    fused_ngp_mlp<<<blocks, 256>>>(texc, W0, W1, W2, AABB, minmax, out, N);
}

// round 4
// speedup vs baseline: 1.4760x; 1.3445x over previous
#include <cuda_runtime.h>
#include <cuda_bf16.h>
#include <stdint.h>

// MLPTexture3D fused instant-NGP hashgrid (L=16, T=2^19) + MLP(32-32-32-9) + sigmoid.
// R4: register diet (bf16x2 packed activations + HFMA2 MLP) -> 4 blocks/SM occupancy.

constexpr int NLVL = 16;
constexpr uint32_t TBL = 1u << 19;
constexpr uint32_t TBLMASK = TBL - 1u;
constexpr uint32_t NSLOT = (uint32_t)NLVL * TBL;

__device__ __align__(16) uint2 gPair[NSLOT];   // 64 MB bf16 pair table

__global__ void __launch_bounds__(256)
repack_grid(const float2* __restrict__ grid)
{
    const uint32_t k = blockIdx.x * 256u + threadIdx.x;
    if (k >= NSLOT) return;
    const uint32_t lk = k & TBLMASK;
    const float2 e0 = __ldcs(grid + k);
    const float2 e1 = (lk + 1u < TBL) ? __ldcs(grid + k + 1u) : e0;
    const __nv_bfloat162 b0 = __float22bfloat162_rn(e0);
    const __nv_bfloat162 b1 = __float22bfloat162_rn(e1);
    uint2 o;
    o.x = *reinterpret_cast<const uint32_t*>(&b0);
    o.y = *reinterpret_cast<const uint32_t*>(&b1);
    gPair[k] = o;
}

__device__ __forceinline__ __nv_bfloat162 u2b(uint32_t u) {
    return *reinterpret_cast<__nv_bfloat162*>(&u);
}

__global__ void __launch_bounds__(256, 4)
fused_ngp_mlp(const float* __restrict__ texc,
              const float* __restrict__ W0,
              const float* __restrict__ W1,
              const float* __restrict__ W2,
              const float* __restrict__ AABB,
              const float* __restrict__ minmax,
              float* __restrict__ out,
              int N)
{
    // Weights repacked to bf16x2: row j of W0/W1 = 16 bf16x2; W2 row = 16.
    __shared__ __align__(16) uint32_t sW0b[512];
    __shared__ __align__(16) uint32_t sW1b[512];
    __shared__ __align__(16) uint32_t sW2b[144];
    __shared__ float sA[6];
    __shared__ float sLo[9];
    __shared__ float sDf[9];

    const int tid = threadIdx.x;
    for (int i = tid; i < 512; i += 256) {
        sW0b[i] = *reinterpret_cast<const uint32_t*>(
            &__floats2bfloat162_rn(W0[2 * i], W0[2 * i + 1]));
        sW1b[i] = *reinterpret_cast<const uint32_t*>(
            &__floats2bfloat162_rn(W1[2 * i], W1[2 * i + 1]));
    }
    if (tid < 144) {
        sW2b[tid] = *reinterpret_cast<const uint32_t*>(
            &__floats2bfloat162_rn(W2[2 * tid], W2[2 * tid + 1]));
    }
    if (tid < 6)  sA[tid] = AABB[tid];
    if (tid < 9)  { float lo = minmax[tid]; sLo[tid] = lo; sDf[tid] = minmax[9 + tid] - lo; }
    __syncthreads();

    const int n = blockIdx.x * 256 + tid;
    if (n >= N) return;

    float ux, uy, uz;
    {
        const float tx = __ldcs(texc + 3 * n + 0);
        const float ty = __ldcs(texc + 3 * n + 1);
        const float tz = __ldcs(texc + 3 * n + 2);
        ux = __saturatef((tx - sA[0]) / (sA[3] - sA[0]));
        uy = __saturatef((ty - sA[1]) / (sA[4] - sA[1]));
        uz = __saturatef((tz - sA[2]) / (sA[5] - sA[2]));
    }

    __nv_bfloat162 fp[16];   // packed per-level features

#pragma unroll
    for (int l = 0; l < NLVL; ++l) {
        const float scale = 16.0f * exp2f((float)l * (8.0f / 15.0f)) - 1.0f;
        const float posx = ux * scale + 0.5f;
        const float posy = uy * scale + 0.5f;
        const float posz = uz * scale + 0.5f;
        const float flx = floorf(posx), fly = floorf(posy), flz = floorf(posz);
        const float rx = posx - flx, ry = posy - fly, rz = posz - flz;
        const uint32_t ix = (uint32_t)flx, iy = (uint32_t)fly, iz = (uint32_t)flz;

        uint32_t slot[4];
        bool hiA[4], hiB[4];
        if (l < 5) {
            const uint32_t R = (l == 0) ? 16u : (l == 1) ? 24u : (l == 2) ? 34u
                              : (l == 3) ? 49u : 71u;
            const uint32_t rm = R - 1u;
            const uint32_t x0 = min(ix, rm),            x1 = min(ix + 1u, rm);
            const uint32_t y0 = min(iy, rm) * R,        y1 = min(iy + 1u, rm) * R;
            const uint32_t z0 = min(iz, rm) * (R * R),  z1 = min(iz + 1u, rm) * (R * R);
            const bool adv = (x1 > x0);
            slot[0] = x0 + y0 + z0;  slot[1] = x0 + y1 + z0;
            slot[2] = x0 + y0 + z1;  slot[3] = x0 + y1 + z1;
#pragma unroll
            for (int c = 0; c < 4; ++c) { hiA[c] = false; hiB[c] = adv; }
        } else {
            const uint32_t hy0 = iy * 2654435761u, hy1 = hy0 + 2654435761u;
            const uint32_t hz0 = iz * 805459861u,  hz1 = hz0 + 805459861u;
            const uint32_t b00 = hy0 ^ hz0, b10 = hy1 ^ hz0;
            const uint32_t b01 = hy0 ^ hz1, b11 = hy1 ^ hz1;
            const uint32_t a0 = (ix ^ b00) & TBLMASK;
            const uint32_t a1 = (ix ^ b10) & TBLMASK;
            const uint32_t a2 = (ix ^ b01) & TBLMASK;
            const uint32_t a3 = (ix ^ b11) & TBLMASK;
            slot[0] = a0 & ~1u; slot[1] = a1 & ~1u;
            slot[2] = a2 & ~1u; slot[3] = a3 & ~1u;
            hiA[0] = a0 & 1u; hiA[1] = a1 & 1u; hiA[2] = a2 & 1u; hiA[3] = a3 & 1u;
#pragma unroll
            for (int c = 0; c < 4; ++c) hiB[c] = !hiA[c];
        }

        const uint2* __restrict__ gl = gPair + (size_t)l * TBL;
        uint2 q[4];
#pragma unroll
        for (int c = 0; c < 4; ++c) q[c] = __ldg(gl + slot[c]);

        const float wx0 = 1.0f - rx, wy0 = 1.0f - ry, wz0 = 1.0f - rz;
        const float pw[4] = { wy0 * wz0, ry * wz0, wy0 * rz, ry * rz };

        float f0 = 0.0f, f1 = 0.0f;
#pragma unroll
        for (int c = 0; c < 4; ++c) {
            const uint32_t pa = hiA[c] ? q[c].y : q[c].x;
            const uint32_t pb = hiB[c] ? q[c].y : q[c].x;
            const float2 va = __bfloat1622float2(u2b(pa));
            const float2 vb = __bfloat1622float2(u2b(pb));
            const float w0c = pw[c] * wx0;
            const float w1c = pw[c] * rx;
            f0 = fmaf(w0c, va.x, f0);  f1 = fmaf(w0c, va.y, f1);
            f0 = fmaf(w1c, vb.x, f0);  f1 = fmaf(w1c, vb.y, f1);
        }
        fp[l] = __floats2bfloat162_rn(f0, f1);
    }

    // ---- MLP layer 0: packed bf16x2 HFMA2 ----
    __nv_bfloat162 hp[16];
    {
        float prev = 0.0f;
#pragma unroll
        for (int j = 0; j < 32; ++j) {
            const uint4* wr = reinterpret_cast<const uint4*>(sW0b + j * 16);
            __nv_bfloat162 acc0 = __floats2bfloat162_rn(0.f, 0.f);
            __nv_bfloat162 acc1 = __floats2bfloat162_rn(0.f, 0.f);
#pragma unroll
            for (int i = 0; i < 4; ++i) {
                const uint4 w = wr[i];
                acc0 = __hfma2(fp[4 * i + 0], u2b(w.x), acc0);
                acc1 = __hfma2(fp[4 * i + 1], u2b(w.y), acc1);
                acc0 = __hfma2(fp[4 * i + 2], u2b(w.z), acc0);
                acc1 = __hfma2(fp[4 * i + 3], u2b(w.w), acc1);
            }
            const float t = fmaxf(__low2float(acc0) + __high2float(acc0)
                                + __low2float(acc1) + __high2float(acc1), 0.0f);
            if (j & 1) hp[j >> 1] = __floats2bfloat162_rn(prev, t);
            else       prev = t;
        }
    }

    // ---- MLP layer 1 ----
    __nv_bfloat162 h2p[16];
    {
        float prev = 0.0f;
#pragma unroll
        for (int j = 0; j < 32; ++j) {
            const uint4* wr = reinterpret_cast<const uint4*>(sW1b + j * 16);
            __nv_bfloat162 acc0 = __floats2bfloat162_rn(0.f, 0.f);
            __nv_bfloat162 acc1 = __floats2bfloat162_rn(0.f, 0.f);
#pragma unroll
            for (int i = 0; i < 4; ++i) {
                const uint4 w = wr[i];
                acc0 = __hfma2(hp[4 * i + 0], u2b(w.x), acc0);
                acc1 = __hfma2(hp[4 * i + 1], u2b(w.y), acc1);
                acc0 = __hfma2(hp[4 * i + 2], u2b(w.z), acc0);
                acc1 = __hfma2(hp[4 * i + 3], u2b(w.w), acc1);
            }
            const float t = fmaxf(__low2float(acc0) + __high2float(acc0)
                                + __low2float(acc1) + __high2float(acc1), 0.0f);
            if (j & 1) h2p[j >> 1] = __floats2bfloat162_rn(prev, t);
            else       prev = t;
        }
    }

    // ---- MLP layer 2 + sigmoid + min/max scale ----
#pragma unroll
    for (int k = 0; k < 9; ++k) {
        const uint4* wr = reinterpret_cast<const uint4*>(sW2b + k * 16);
        __nv_bfloat162 acc0 = __floats2bfloat162_rn(0.f, 0.f);
        __nv_bfloat162 acc1 = __floats2bfloat162_rn(0.f, 0.f);
#pragma unroll
        for (int i = 0; i < 4; ++i) {
            const uint4 w = wr[i];
            acc0 = __hfma2(h2p[4 * i + 0], u2b(w.x), acc0);
            acc1 = __hfma2(h2p[4 * i + 1], u2b(w.y), acc1);
            acc0 = __hfma2(h2p[4 * i + 2], u2b(w.z), acc0);
            acc1 = __hfma2(h2p[4 * i + 3], u2b(w.w), acc1);
        }
        const float o = __low2float(acc0) + __high2float(acc0)
                      + __low2float(acc1) + __high2float(acc1);
        const float sig = 1.0f / (1.0f + __expf(-o));
        __stcs(out + (size_t)n * 9 + k, fmaf(sig, sDf[k], sLo[k]));
    }
}

extern "C" void kernel_launch(void* const* d_in, const int* in_sizes, int n_in,
                              void* d_out, int out_size) {
    const float* texc   = (const float*)d_in[0];
    const float* grid   = (const float*)d_in[1];
    const float* W0     = (const float*)d_in[2];
    const float* W1     = (const float*)d_in[3];
    const float* W2     = (const float*)d_in[4];
    const float* AABB   = (const float*)d_in[5];
    const float* minmax = (const float*)d_in[6];
    float* out = (float*)d_out;

    const int N = in_sizes[0] / 3;

    repack_grid<<<(NSLOT + 255u) / 256u, 256>>>(
        reinterpret_cast<const float2*>(grid));

    const int blocks = (N + 255) / 256;
    fused_ngp_mlp<<<blocks, 256>>>(texc, W0, W1, W2, AABB, minmax, out, N);
}

// round 5
// speedup vs baseline: 1.5566x; 1.0546x over previous
#include <cuda_runtime.h>
#include <cuda_bf16.h>
#include <stdint.h>

// MLPTexture3D fused instant-NGP hashgrid (L=16, T=2^19) + MLP(32-32-32-9) + sigmoid.
// R5: SMEM-staged coalesced texc loads + output stores (-15% L1 wavefronts).

constexpr int NLVL = 16;
constexpr uint32_t TBL = 1u << 19;
constexpr uint32_t TBLMASK = TBL - 1u;
constexpr uint32_t NSLOT = (uint32_t)NLVL * TBL;

__device__ __align__(16) uint2 gPair[NSLOT];   // 64 MB bf16 pair table

__global__ void __launch_bounds__(256)
repack_grid(const float2* __restrict__ grid)
{
    const uint32_t k = blockIdx.x * 256u + threadIdx.x;
    if (k >= NSLOT) return;
    const uint32_t lk = k & TBLMASK;
    const float2 e0 = __ldcs(grid + k);
    const float2 e1 = (lk + 1u < TBL) ? __ldcs(grid + k + 1u) : e0;
    const __nv_bfloat162 b0 = __float22bfloat162_rn(e0);
    const __nv_bfloat162 b1 = __float22bfloat162_rn(e1);
    uint2 o;
    o.x = *reinterpret_cast<const uint32_t*>(&b0);
    o.y = *reinterpret_cast<const uint32_t*>(&b1);
    gPair[k] = o;
}

__device__ __forceinline__ __nv_bfloat162 u2b(uint32_t u) {
    return *reinterpret_cast<__nv_bfloat162*>(&u);
}

__global__ void __launch_bounds__(256, 4)
fused_ngp_mlp(const float* __restrict__ texc,
              const float* __restrict__ W0,
              const float* __restrict__ W1,
              const float* __restrict__ W2,
              const float* __restrict__ AABB,
              const float* __restrict__ minmax,
              float* __restrict__ out,
              int N)
{
    __shared__ __align__(16) uint32_t sW0b[512];
    __shared__ __align__(16) uint32_t sW1b[512];
    __shared__ __align__(16) uint32_t sW2b[144];
    __shared__ __align__(16) float sTex[768];      // 256 points x 3
    __shared__ __align__(16) float sOut[2304];     // 256 points x 9
    __shared__ float sA[6];
    __shared__ float sLo[9];
    __shared__ float sDf[9];

    const int tid = threadIdx.x;
    for (int i = tid; i < 512; i += 256) {
        sW0b[i] = *reinterpret_cast<const uint32_t*>(
            &__floats2bfloat162_rn(W0[2 * i], W0[2 * i + 1]));
        sW1b[i] = *reinterpret_cast<const uint32_t*>(
            &__floats2bfloat162_rn(W1[2 * i], W1[2 * i + 1]));
    }
    if (tid < 144) {
        sW2b[tid] = *reinterpret_cast<const uint32_t*>(
            &__floats2bfloat162_rn(W2[2 * tid], W2[2 * tid + 1]));
    }
    if (tid < 6)  sA[tid] = AABB[tid];
    if (tid < 9)  { float lo = minmax[tid]; sLo[tid] = lo; sDf[tid] = minmax[9 + tid] - lo; }

    const int base = blockIdx.x * 256;
    const bool fullBlock = (base + 256 <= N);

    // Coalesced texc stage: 768 contiguous floats = 192 float4.
    if (fullBlock) {
        const float4* t4 = reinterpret_cast<const float4*>(texc + (size_t)base * 3);
        if (tid < 192) {
            const float4 v = __ldcs(t4 + tid);
            reinterpret_cast<float4*>(sTex)[tid] = v;
        }
    } else {
        const int cnt = (N - base) * 3;
        for (int i = tid; i < cnt; i += 256) sTex[i] = texc[(size_t)base * 3 + i];
    }
    __syncthreads();

    const int n = base + tid;
    if (n < N) {
        const float ux = __saturatef((sTex[3 * tid + 0] - sA[0]) / (sA[3] - sA[0]));
        const float uy = __saturatef((sTex[3 * tid + 1] - sA[1]) / (sA[4] - sA[1]));
        const float uz = __saturatef((sTex[3 * tid + 2] - sA[2]) / (sA[5] - sA[2]));

        __nv_bfloat162 fp[16];   // packed per-level features

#pragma unroll
        for (int l = 0; l < NLVL; ++l) {
            const float scale = 16.0f * exp2f((float)l * (8.0f / 15.0f)) - 1.0f;
            const float posx = ux * scale + 0.5f;
            const float posy = uy * scale + 0.5f;
            const float posz = uz * scale + 0.5f;
            const float flx = floorf(posx), fly = floorf(posy), flz = floorf(posz);
            const float rx = posx - flx, ry = posy - fly, rz = posz - flz;
            const uint32_t ix = (uint32_t)flx, iy = (uint32_t)fly, iz = (uint32_t)flz;

            uint32_t slot[4];
            bool hiA[4], hiB[4];
            if (l < 5) {
                const uint32_t R = (l == 0) ? 16u : (l == 1) ? 24u : (l == 2) ? 34u
                                  : (l == 3) ? 49u : 71u;
                const uint32_t rm = R - 1u;
                const uint32_t x0 = min(ix, rm),            x1 = min(ix + 1u, rm);
                const uint32_t y0 = min(iy, rm) * R,        y1 = min(iy + 1u, rm) * R;
                const uint32_t z0 = min(iz, rm) * (R * R),  z1 = min(iz + 1u, rm) * (R * R);
                const bool adv = (x1 > x0);
                slot[0] = x0 + y0 + z0;  slot[1] = x0 + y1 + z0;
                slot[2] = x0 + y0 + z1;  slot[3] = x0 + y1 + z1;
#pragma unroll
                for (int c = 0; c < 4; ++c) { hiA[c] = false; hiB[c] = adv; }
            } else {
                const uint32_t hy0 = iy * 2654435761u, hy1 = hy0 + 2654435761u;
                const uint32_t hz0 = iz * 805459861u,  hz1 = hz0 + 805459861u;
                const uint32_t b00 = hy0 ^ hz0, b10 = hy1 ^ hz0;
                const uint32_t b01 = hy0 ^ hz1, b11 = hy1 ^ hz1;
                const uint32_t a0 = (ix ^ b00) & TBLMASK;
                const uint32_t a1 = (ix ^ b10) & TBLMASK;
                const uint32_t a2 = (ix ^ b01) & TBLMASK;
                const uint32_t a3 = (ix ^ b11) & TBLMASK;
                slot[0] = a0 & ~1u; slot[1] = a1 & ~1u;
                slot[2] = a2 & ~1u; slot[3] = a3 & ~1u;
                hiA[0] = a0 & 1u; hiA[1] = a1 & 1u;
                hiA[2] = a2 & 1u; hiA[3] = a3 & 1u;
#pragma unroll
                for (int c = 0; c < 4; ++c) hiB[c] = !hiA[c];
            }

            const uint2* __restrict__ gl = gPair + (size_t)l * TBL;
            uint2 q[4];
#pragma unroll
            for (int c = 0; c < 4; ++c) q[c] = __ldg(gl + slot[c]);

            const float wx0 = 1.0f - rx, wy0 = 1.0f - ry, wz0 = 1.0f - rz;
            const float pw[4] = { wy0 * wz0, ry * wz0, wy0 * rz, ry * rz };

            float f0 = 0.0f, f1 = 0.0f;
#pragma unroll
            for (int c = 0; c < 4; ++c) {
                const uint32_t pa = hiA[c] ? q[c].y : q[c].x;
                const uint32_t pb = hiB[c] ? q[c].y : q[c].x;
                const float2 va = __bfloat1622float2(u2b(pa));
                const float2 vb = __bfloat1622float2(u2b(pb));
                const float w0c = pw[c] * wx0;
                const float w1c = pw[c] * rx;
                f0 = fmaf(w0c, va.x, f0);  f1 = fmaf(w0c, va.y, f1);
                f0 = fmaf(w1c, vb.x, f0);  f1 = fmaf(w1c, vb.y, f1);
            }
            fp[l] = __floats2bfloat162_rn(f0, f1);
        }

        // ---- MLP layer 0 (bf16x2 HFMA2) ----
        __nv_bfloat162 hp[16];
        {
            float prev = 0.0f;
#pragma unroll
            for (int j = 0; j < 32; ++j) {
                const uint4* wr = reinterpret_cast<const uint4*>(sW0b + j * 16);
                __nv_bfloat162 acc0 = __floats2bfloat162_rn(0.f, 0.f);
                __nv_bfloat162 acc1 = __floats2bfloat162_rn(0.f, 0.f);
#pragma unroll
                for (int i = 0; i < 4; ++i) {
                    const uint4 w = wr[i];
                    acc0 = __hfma2(fp[4 * i + 0], u2b(w.x), acc0);
                    acc1 = __hfma2(fp[4 * i + 1], u2b(w.y), acc1);
                    acc0 = __hfma2(fp[4 * i + 2], u2b(w.z), acc0);
                    acc1 = __hfma2(fp[4 * i + 3], u2b(w.w), acc1);
                }
                const float t = fmaxf(__low2float(acc0) + __high2float(acc0)
                                    + __low2float(acc1) + __high2float(acc1), 0.0f);
                if (j & 1) hp[j >> 1] = __floats2bfloat162_rn(prev, t);
                else       prev = t;
            }
        }

        // ---- MLP layer 1 ----
        __nv_bfloat162 h2p[16];
        {
            float prev = 0.0f;
#pragma unroll
            for (int j = 0; j < 32; ++j) {
                const uint4* wr = reinterpret_cast<const uint4*>(sW1b + j * 16);
                __nv_bfloat162 acc0 = __floats2bfloat162_rn(0.f, 0.f);
                __nv_bfloat162 acc1 = __floats2bfloat162_rn(0.f, 0.f);
#pragma unroll
                for (int i = 0; i < 4; ++i) {
                    const uint4 w = wr[i];
                    acc0 = __hfma2(hp[4 * i + 0], u2b(w.x), acc0);
                    acc1 = __hfma2(hp[4 * i + 1], u2b(w.y), acc1);
                    acc0 = __hfma2(hp[4 * i + 2], u2b(w.z), acc0);
                    acc1 = __hfma2(hp[4 * i + 3], u2b(w.w), acc1);
                }
                const float t = fmaxf(__low2float(acc0) + __high2float(acc0)
                                    + __low2float(acc1) + __high2float(acc1), 0.0f);
                if (j & 1) h2p[j >> 1] = __floats2bfloat162_rn(prev, t);
                else       prev = t;
            }
        }

        // ---- MLP layer 2 + sigmoid + scale -> SMEM stage ----
#pragma unroll
        for (int k = 0; k < 9; ++k) {
            const uint4* wr = reinterpret_cast<const uint4*>(sW2b + k * 16);
            __nv_bfloat162 acc0 = __floats2bfloat162_rn(0.f, 0.f);
            __nv_bfloat162 acc1 = __floats2bfloat162_rn(0.f, 0.f);
#pragma unroll
            for (int i = 0; i < 4; ++i) {
                const uint4 w = wr[i];
                acc0 = __hfma2(h2p[4 * i + 0], u2b(w.x), acc0);
                acc1 = __hfma2(h2p[4 * i + 1], u2b(w.y), acc1);
                acc0 = __hfma2(h2p[4 * i + 2], u2b(w.z), acc0);
                acc1 = __hfma2(h2p[4 * i + 3], u2b(w.w), acc1);
            }
            const float o = __low2float(acc0) + __high2float(acc0)
                          + __low2float(acc1) + __high2float(acc1);
            const float sig = 1.0f / (1.0f + __expf(-o));
            sOut[tid * 9 + k] = fmaf(sig, sDf[k], sLo[k]);   // stride 9: bank-safe
        }
    }
    __syncthreads();

    // Coalesced output: 2304 contiguous floats = 576 float4.
    if (fullBlock) {
        float4* o4 = reinterpret_cast<float4*>(out + (size_t)base * 9);
        const float4* s4 = reinterpret_cast<const float4*>(sOut);
#pragma unroll
        for (int i = 0; i < 3; ++i) {
            const int idx = tid + 256 * i;
            if (idx < 576) __stcs(o4 + idx, s4[idx]);
        }
    } else {
        const int cnt = (N - base) * 9;
        for (int i = tid; i < cnt; i += 256) out[(size_t)base * 9 + i] = sOut[i];
    }
}

extern "C" void kernel_launch(void* const* d_in, const int* in_sizes, int n_in,
                              void* d_out, int out_size) {
    const float* texc   = (const float*)d_in[0];
    const float* grid   = (const float*)d_in[1];
    const float* W0     = (const float*)d_in[2];
    const float* W1     = (const float*)d_in[3];
    const float* W2     = (const float*)d_in[4];
    const float* AABB   = (const float*)d_in[5];
    const float* minmax = (const float*)d_in[6];
    float* out = (float*)d_out;

    const int N = in_sizes[0] / 3;

    repack_grid<<<(NSLOT + 255u) / 256u, 256>>>(
        reinterpret_cast<const float2*>(grid));

    const int blocks = (N + 255) / 256;
    fused_ngp_mlp<<<blocks, 256>>>(texc, W0, W1, W2, AABB, minmax, out, N);
}

// round 6
// speedup vs baseline: 1.6622x; 1.0678x over previous
#include <cuda_runtime.h>
#include <cuda_bf16.h>
#include <stdint.h>

// MLPTexture3D fused instant-NGP hashgrid (L=16, T=2^19) + MLP(32-32-32-9) + sigmoid.
// R6: weights in __constant__ (off L1tex), trilinear interp in packed bf16x2 HFMA2.

constexpr int NLVL = 16;
constexpr uint32_t TBL = 1u << 19;
constexpr uint32_t TBLMASK = TBL - 1u;
constexpr uint32_t NSLOT = (uint32_t)NLVL * TBL;

__device__ __align__(16) uint2 gPair[NSLOT];   // 64 MB bf16 pair table

struct __align__(16) KConsts {
    uint32_t w0[512];   // W0 rows as bf16x2
    uint32_t w1[512];
    uint32_t w2[144];
    float A[6];
    float lo[9];
    float df[9];
};
__constant__ KConsts cc;
__device__ KConsts gStage;

__global__ void __launch_bounds__(256)
repack_grid(const float2* __restrict__ grid)
{
    const uint32_t k = blockIdx.x * 256u + threadIdx.x;
    if (k >= NSLOT) return;
    const uint32_t lk = k & TBLMASK;
    const float2 e0 = __ldcs(grid + k);
    const float2 e1 = (lk + 1u < TBL) ? __ldcs(grid + k + 1u) : e0;
    const __nv_bfloat162 b0 = __float22bfloat162_rn(e0);
    const __nv_bfloat162 b1 = __float22bfloat162_rn(e1);
    uint2 o;
    o.x = *reinterpret_cast<const uint32_t*>(&b0);
    o.y = *reinterpret_cast<const uint32_t*>(&b1);
    gPair[k] = o;
}

__global__ void __launch_bounds__(256)
prep_consts(const float* __restrict__ W0, const float* __restrict__ W1,
            const float* __restrict__ W2, const float* __restrict__ AABB,
            const float* __restrict__ minmax)
{
    const int t = threadIdx.x;
    for (int i = t; i < 512; i += 256) {
        __nv_bfloat162 a = __floats2bfloat162_rn(W0[2 * i], W0[2 * i + 1]);
        __nv_bfloat162 b = __floats2bfloat162_rn(W1[2 * i], W1[2 * i + 1]);
        gStage.w0[i] = *reinterpret_cast<const uint32_t*>(&a);
        gStage.w1[i] = *reinterpret_cast<const uint32_t*>(&b);
    }
    if (t < 144) {
        __nv_bfloat162 a = __floats2bfloat162_rn(W2[2 * t], W2[2 * t + 1]);
        gStage.w2[t] = *reinterpret_cast<const uint32_t*>(&a);
    }
    if (t < 6) gStage.A[t] = AABB[t];
    if (t < 9) { float lo = minmax[t]; gStage.lo[t] = lo; gStage.df[t] = minmax[9 + t] - lo; }
}

__device__ __forceinline__ __nv_bfloat162 u2b(uint32_t u) {
    return *reinterpret_cast<__nv_bfloat162*>(&u);
}

__global__ void __launch_bounds__(256, 4)
fused_ngp_mlp(const float* __restrict__ texc,
              float* __restrict__ out,
              int N)
{
    __shared__ __align__(16) float sTex[768];      // 256 points x 3
    __shared__ __align__(16) float sOut[2304];     // 256 points x 9

    const int tid = threadIdx.x;
    const int base = blockIdx.x * 256;
    const bool fullBlock = (base + 256 <= N);

    if (fullBlock) {
        const float4* t4 = reinterpret_cast<const float4*>(texc + (size_t)base * 3);
        if (tid < 192) {
            const float4 v = __ldcs(t4 + tid);
            reinterpret_cast<float4*>(sTex)[tid] = v;
        }
    } else {
        const int cnt = (N - base) * 3;
        for (int i = tid; i < cnt; i += 256) sTex[i] = texc[(size_t)base * 3 + i];
    }
    __syncthreads();

    const int n = base + tid;
    if (n < N) {
        const float ux = __saturatef((sTex[3 * tid + 0] - cc.A[0]) / (cc.A[3] - cc.A[0]));
        const float uy = __saturatef((sTex[3 * tid + 1] - cc.A[1]) / (cc.A[4] - cc.A[1]));
        const float uz = __saturatef((sTex[3 * tid + 2] - cc.A[2]) / (cc.A[5] - cc.A[2]));

        __nv_bfloat162 fp[16];   // packed per-level features

#pragma unroll
        for (int l = 0; l < NLVL; ++l) {
            const float scale = 16.0f * exp2f((float)l * (8.0f / 15.0f)) - 1.0f;
            const float posx = ux * scale + 0.5f;
            const float posy = uy * scale + 0.5f;
            const float posz = uz * scale + 0.5f;
            const float flx = floorf(posx), fly = floorf(posy), flz = floorf(posz);
            const float rx = posx - flx, ry = posy - fly, rz = posz - flz;
            const uint32_t ix = (uint32_t)flx, iy = (uint32_t)fly, iz = (uint32_t)flz;

            uint32_t slot[4];
            uint32_t odd[4];        // hashed: x0-corner index parity
            bool adv = true;        // dense: x1 not clamped
            if (l < 5) {
                const uint32_t R = (l == 0) ? 16u : (l == 1) ? 24u : (l == 2) ? 34u
                                  : (l == 3) ? 49u : 71u;
                const uint32_t rm = R - 1u;
                const uint32_t x0 = min(ix, rm),            x1 = min(ix + 1u, rm);
                const uint32_t y0 = min(iy, rm) * R,        y1 = min(iy + 1u, rm) * R;
                const uint32_t z0 = min(iz, rm) * (R * R),  z1 = min(iz + 1u, rm) * (R * R);
                adv = (x1 > x0);
                slot[0] = x0 + y0 + z0;  slot[1] = x0 + y1 + z0;
                slot[2] = x0 + y0 + z1;  slot[3] = x0 + y1 + z1;
                odd[0] = odd[1] = odd[2] = odd[3] = 0u;
            } else {
                const uint32_t hy0 = iy * 2654435761u, hy1 = hy0 + 2654435761u;
                const uint32_t hz0 = iz * 805459861u,  hz1 = hz0 + 805459861u;
                const uint32_t b00 = hy0 ^ hz0, b10 = hy1 ^ hz0;
                const uint32_t b01 = hy0 ^ hz1, b11 = hy1 ^ hz1;
                const uint32_t a0 = (ix ^ b00) & TBLMASK;
                const uint32_t a1 = (ix ^ b10) & TBLMASK;
                const uint32_t a2 = (ix ^ b01) & TBLMASK;
                const uint32_t a3 = (ix ^ b11) & TBLMASK;
                slot[0] = a0 & ~1u; slot[1] = a1 & ~1u;
                slot[2] = a2 & ~1u; slot[3] = a3 & ~1u;
                odd[0] = a0 & 1u;  odd[1] = a1 & 1u;
                odd[2] = a2 & 1u;  odd[3] = a3 & 1u;
            }

            const uint2* __restrict__ gl = gPair + (size_t)l * TBL;
            uint2 q[4];
#pragma unroll
            for (int c = 0; c < 4; ++c) q[c] = __ldg(gl + slot[c]);

            const float wx0 = 1.0f - rx, wy0 = 1.0f - ry, wz0 = 1.0f - rz;
            const float pw[4] = { wy0 * wz0, ry * wz0, wy0 * rz, ry * rz };

            __nv_bfloat162 facc = __float2bfloat162_rn(0.0f);
#pragma unroll
            for (int c = 0; c < 4; ++c) {
                const float w0c = pw[c] * wx0;     // x0-corner weight
                const float w1c = pw[c] * rx;      // x1-corner weight
                float we, wo;                      // weights for q.x / q.y entries
                if (l < 5) {
                    we = adv ? w0c : (w0c + w1c);
                    wo = adv ? w1c : 0.0f;
                } else {
                    we = odd[c] ? w1c : w0c;
                    wo = odd[c] ? w0c : w1c;
                }
                facc = __hfma2(__float2bfloat162_rn(we), u2b(q[c].x), facc);
                facc = __hfma2(__float2bfloat162_rn(wo), u2b(q[c].y), facc);
            }
            fp[l] = facc;
        }

        // ---- MLP layer 0 (bf16x2 HFMA2, weights from constant bank) ----
        __nv_bfloat162 hp[16];
        {
            float prev = 0.0f;
#pragma unroll
            for (int j = 0; j < 32; ++j) {
                const uint4* wr = reinterpret_cast<const uint4*>(cc.w0 + j * 16);
                __nv_bfloat162 acc0 = __float2bfloat162_rn(0.0f);
                __nv_bfloat162 acc1 = __float2bfloat162_rn(0.0f);
#pragma unroll
                for (int i = 0; i < 4; ++i) {
                    const uint4 w = wr[i];
                    acc0 = __hfma2(fp[4 * i + 0], u2b(w.x), acc0);
                    acc1 = __hfma2(fp[4 * i + 1], u2b(w.y), acc1);
                    acc0 = __hfma2(fp[4 * i + 2], u2b(w.z), acc0);
                    acc1 = __hfma2(fp[4 * i + 3], u2b(w.w), acc1);
                }
                const float t = fmaxf(__low2float(acc0) + __high2float(acc0)
                                    + __low2float(acc1) + __high2float(acc1), 0.0f);
                if (j & 1) hp[j >> 1] = __floats2bfloat162_rn(prev, t);
                else       prev = t;
            }
        }

        // ---- MLP layer 1 ----
        __nv_bfloat162 h2p[16];
        {
            float prev = 0.0f;
#pragma unroll
            for (int j = 0; j < 32; ++j) {
                const uint4* wr = reinterpret_cast<const uint4*>(cc.w1 + j * 16);
                __nv_bfloat162 acc0 = __float2bfloat162_rn(0.0f);
                __nv_bfloat162 acc1 = __float2bfloat162_rn(0.0f);
#pragma unroll
                for (int i = 0; i < 4; ++i) {
                    const uint4 w = wr[i];
                    acc0 = __hfma2(hp[4 * i + 0], u2b(w.x), acc0);
                    acc1 = __hfma2(hp[4 * i + 1], u2b(w.y), acc1);
                    acc0 = __hfma2(hp[4 * i + 2], u2b(w.z), acc0);
                    acc1 = __hfma2(hp[4 * i + 3], u2b(w.w), acc1);
                }
                const float t = fmaxf(__low2float(acc0) + __high2float(acc0)
                                    + __low2float(acc1) + __high2float(acc1), 0.0f);
                if (j & 1) h2p[j >> 1] = __floats2bfloat162_rn(prev, t);
                else       prev = t;
            }
        }

        // ---- MLP layer 2 + sigmoid + scale -> SMEM stage ----
#pragma unroll
        for (int k = 0; k < 9; ++k) {
            const uint4* wr = reinterpret_cast<const uint4*>(cc.w2 + k * 16);
            __nv_bfloat162 acc0 = __float2bfloat162_rn(0.0f);
            __nv_bfloat162 acc1 = __float2bfloat162_rn(0.0f);
#pragma unroll
            for (int i = 0; i < 4; ++i) {
                const uint4 w = wr[i];
                acc0 = __hfma2(h2p[4 * i + 0], u2b(w.x), acc0);
                acc1 = __hfma2(h2p[4 * i + 1], u2b(w.y), acc1);
                acc0 = __hfma2(h2p[4 * i + 2], u2b(w.z), acc0);
                acc1 = __hfma2(h2p[4 * i + 3], u2b(w.w), acc1);
            }
            const float o = __low2float(acc0) + __high2float(acc0)
                          + __low2float(acc1) + __high2float(acc1);
            const float sig = 1.0f / (1.0f + __expf(-o));
            sOut[tid * 9 + k] = fmaf(sig, cc.df[k], cc.lo[k]);
        }
    }
    __syncthreads();

    if (fullBlock) {
        float4* o4 = reinterpret_cast<float4*>(out + (size_t)base * 9);
        const float4* s4 = reinterpret_cast<const float4*>(sOut);
#pragma unroll
        for (int i = 0; i < 3; ++i) {
            const int idx = tid + 256 * i;
            if (idx < 576) __stcs(o4 + idx, s4[idx]);
        }
    } else {
        const int cnt = (N - base) * 9;
        for (int i = tid; i < cnt; i += 256) out[(size_t)base * 9 + i] = sOut[i];
    }
}

extern "C" void kernel_launch(void* const* d_in, const int* in_sizes, int n_in,
                              void* d_out, int out_size) {
    const float* texc   = (const float*)d_in[0];
    const float* grid   = (const float*)d_in[1];
    const float* W0     = (const float*)d_in[2];
    const float* W1     = (const float*)d_in[3];
    const float* W2     = (const float*)d_in[4];
    const float* AABB   = (const float*)d_in[5];
    const float* minmax = (const float*)d_in[6];
    float* out = (float*)d_out;

    const int N = in_sizes[0] / 3;

    repack_grid<<<(NSLOT + 255u) / 256u, 256>>>(
        reinterpret_cast<const float2*>(grid));
    prep_consts<<<1, 256>>>(W0, W1, W2, AABB, minmax);

    void* stagePtr = nullptr;
    cudaGetSymbolAddress(&stagePtr, gStage);
    cudaMemcpyToSymbolAsync(cc, stagePtr, sizeof(KConsts), 0,
                            cudaMemcpyDeviceToDevice, 0);

    const int blocks = (N + 255) / 256;
    fused_ngp_mlp<<<blocks, 256>>>(texc, out, N);
}